// round 12
// baseline (speedup 1.0000x reference)
#include <cuda_runtime.h>
#include <cuda_fp16.h>

// Gridding R11: R10 quarter-split 2-RED/point fp16x2 parity scatter,
// scatter reworked to 4 points/thread (float4 loads, 8 independent REDs).

#define GB 64
#define GBQ 16
#define GN 65536
#define GS 64
#define GRID_CELLS  (GS * GS * GS)
#define QTR_PTS     (GBQ * GN)                  // 1048576
#define PLANE_WORDS 2048
#define GRID_WORDS  ((size_t)GBQ * GS * PLANE_WORDS)  // 8.4 MB words

__device__ unsigned int g_S[4 * GRID_WORDS];    // 33.5 MB, 4 parity grids

// ---------------------------------------------------------------- scatter
__device__ __forceinline__ void scatter_point(float px, float py, float pz,
                                              int b) {
    if (fabsf(px) + fabsf(py) + fabsf(pz) == 0.0f) return;

    float lx = floorf(px), ly = floorf(py), lz = floorf(pz);
    float fx = px - lx, fy = py - ly, fz = pz - lz;

    int ix = (int)lx + 32;                      // uniform input: [0,63]
    int iy = (int)ly + 32;
    int iz = (int)lz + 32;

    float wy0 = 1.0f - fy, wy1 = fy;
    float wz0 = 1.0f - fz, wz1 = fz;

    float a00 = wy0 * wz0, a01 = wy0 * wz1;
    float a10 = wy1 * wz0, a11 = wy1 * wz1;

    int p = ((iy & 1) << 1) | (iz & 1);
    unsigned int* base = g_S + (size_t)p * GRID_WORDS;
    int zw = iz >> 1;
    int ypair = iy & ~1;

    float wx[2] = {1.0f - fx, fx};

    #pragma unroll
    for (int i = 0; i < 2; i++) {
        int X = ix + i;
        if (X >= GS) continue;
        float w = wx[i];
        __half2 h0 = __floats2half2_rn(w * a00, w * a01);
        __half2 h1 = __floats2half2_rn(w * a10, w * a11);
        unsigned int r0 = *(unsigned int*)&h0;
        unsigned int r1 = *(unsigned int*)&h1;
        size_t word = (((size_t)(b * GS + X) * 32 + zw) << 6) + ypair;
        asm volatile("red.global.add.noftz.v2.f16x2 [%0], {%1, %2};"
                     :: "l"(base + word), "r"(r0), "r"(r1) : "memory");
    }
}

__global__ __launch_bounds__(256) void scatter_kernel(const float4* __restrict__ pt) {
    // Each thread handles 4 consecutive points = 48B = 3 float4 loads.
    int t = blockIdx.x * blockDim.x + threadIdx.x;   // 0 .. QTR_PTS/4-1
    int p0 = t << 2;                                 // first point index
    int b = p0 >> 16;                                // 4 pts never straddle batch

    float4 v0 = pt[t * 3 + 0];   // p0.xyz, p1.x
    float4 v1 = pt[t * 3 + 1];   // p1.yz, p2.xy
    float4 v2 = pt[t * 3 + 2];   // p2.z, p3.xyz

    const float S = 32.0f;
    scatter_point(v0.x * S, v0.y * S, v0.z * S, b);
    scatter_point(v0.w * S, v1.x * S, v1.y * S, b);
    scatter_point(v1.z * S, v1.w * S, v2.x * S, b);
    scatter_point(v2.y * S, v2.z * S, v2.w * S, b);
}

// ---------------------------------------------------------------- combine
__device__ __forceinline__ float half_of(unsigned int w, int k) {
    __half2 h = *(__half2*)&w;
    return k ? __high2float(h) : __low2float(h);
}

__global__ __launch_bounds__(256) void combine_kernel(float* __restrict__ out) {
    __shared__ unsigned int s[4][PLANE_WORDS];
    int cta = blockIdx.x;                       // b_local*64 + X
    int t = threadIdx.x;
    size_t pbase = (size_t)cta * PLANE_WORDS;

    uint4 v[4][2];
    #pragma unroll
    for (int g = 0; g < 4; g++) {
        uint4* gp = (uint4*)(g_S + (size_t)g * GRID_WORDS + pbase);
        #pragma unroll
        for (int i = 0; i < 2; i++) v[g][i] = gp[t + i * 256];
    }
    #pragma unroll
    for (int g = 0; g < 4; g++) {
        uint4* sp = (uint4*)s[g];
        uint4* gp = (uint4*)(g_S + (size_t)g * GRID_WORDS + pbase);
        #pragma unroll
        for (int i = 0; i < 2; i++) {
            sp[t + i * 256] = v[g][i];
            gp[t + i * 256] = make_uint4(0u, 0u, 0u, 0u);
        }
    }
    __syncthreads();

    int Y = t >> 2;
    int Z0 = (t & 3) << 4;

    float res[16];
    #pragma unroll
    for (int i = 0; i < 16; i++) {
        int Z = Z0 + i;
        float r = half_of(s[0][(Z >> 1) * 64 + Y], Z & 1);
        if (Z > 0)
            r += half_of(s[1][((Z - 1) >> 1) * 64 + Y], (Z - 1) & 1);
        if (Y > 0) {
            r += half_of(s[2][(Z >> 1) * 64 + (Y - 1)], Z & 1);
            if (Z > 0)
                r += half_of(s[3][((Z - 1) >> 1) * 64 + (Y - 1)], (Z - 1) & 1);
        }
        res[i] = r;
    }

    float4* o = (float4*)(out + ((size_t)cta * 64 + Y) * 64 + Z0);
    o[0] = make_float4(res[0],  res[1],  res[2],  res[3]);
    o[1] = make_float4(res[4],  res[5],  res[6],  res[7]);
    o[2] = make_float4(res[8],  res[9],  res[10], res[11]);
    o[3] = make_float4(res[12], res[13], res[14], res[15]);
}

extern "C" void kernel_launch(void* const* d_in, const int* in_sizes, int n_in,
                              void* d_out, int out_size) {
    const float* pt = (const float*)d_in[0];
    float* out = (float*)d_out;

    int threads = 256;
    int sthreads_total = QTR_PTS / 4;                 // 4 pts per thread
    int sblocks = (sthreads_total + threads - 1) / threads;

    for (int q = 0; q < 4; q++) {
        const float4* ptq = (const float4*)(pt + (size_t)q * GBQ * GN * 3);
        float* outq = out + (size_t)q * GBQ * GRID_CELLS;
        scatter_kernel<<<sblocks, threads>>>(ptq);
        combine_kernel<<<GBQ * GS, 256>>>(outq);
    }
}